// round 14
// baseline (speedup 1.0000x reference)
#include <cuda_runtime.h>

// RuleGraphConvLayer — GB300 sm_103a, round 14
//
// Y = feat @ Wn81 pre-projection:
//   out[n] = Ps[n] + sum_e s_e*Y[dst_e] + c_n*(Y[n] - f0*Wn0 - f1*Wn1 - f2*Wn2)
//            + bagg[n] @ Wb
//
// R14 = R13 + aggcomb re-mapped: half-warp per edge (even/odd split), float4
// per lane (4 channels). Halves loop iterations + instruction count, doubles
// edge-level MLP; epilogue in float4 on 16 lanes (half the issue slots).
// Everything else byte-identical to R13.
// 4 launches: repack+zero+hist | scan1 | scatter∪proj(+bond REDs) | aggcomb.

#define NF 81
#define FP 84      // padded feat pitch (336 B, 21 float4)
#define NB 22
#define BGP 24     // bagg pitch (96 B)
#define OC 64

#define MAX_NODES 100000
#define MAX_EDGES 800000

#define SCAN_T 1024
#define SCAN_E 4
#define SCAN_B (SCAN_T * SCAN_E)   // 4096

__device__ __align__(16) float g_featp[MAX_NODES * FP];
__device__ __align__(16) float g_Y[MAX_NODES * OC];
__device__ __align__(16) float g_Ps[MAX_NODES * OC];
__device__ __align__(16) float g_bagg[MAX_NODES * BGP];
__device__ __align__(8)  int2  g_sorted[MAX_EDGES];   // {dst*256, s_bits}
__device__ int g_hist[MAX_NODES];      // zero at load; scan1 zeroes; K4 re-zeroes
__device__ int g_start[MAX_NODES];     // block-LOCAL exclusive prefix
__device__ int g_bsum[64];

// ---------------------------------------------------------------------------
// K1: repack feat -> g_featp | zero g_bagg | src histogram  (3 block flavors)
// ---------------------------------------------------------------------------
__global__ void repack_hist_kernel(const float* __restrict__ feat,
                                   const int* __restrict__ src,
                                   int n_nodes, int n_edges,
                                   int rblocks, int zblocks) {
    int b = blockIdx.x;
    int t = threadIdx.x;
    if (b < rblocks) {
        int j = b * 256 + t;
        int total = n_nodes * (FP / 4);
        if (j < total) {
            int n = j / (FP / 4);
            int q = j - n * (FP / 4);
            int k = q * 4;
            const float* fr = feat + (size_t)n * NF;
            float4 v;
            v.x = (k + 0 < NF) ? __ldg(fr + k + 0) : 0.f;
            v.y = (k + 1 < NF) ? __ldg(fr + k + 1) : 0.f;
            v.z = (k + 2 < NF) ? __ldg(fr + k + 2) : 0.f;
            v.w = (k + 3 < NF) ? __ldg(fr + k + 3) : 0.f;
            reinterpret_cast<float4*>(g_featp)[j] = v;
        }
    } else if (b < rblocks + zblocks) {
        int j = (b - rblocks) * 256 + t;
        if (j < n_nodes * (BGP / 4))
            reinterpret_cast<float4*>(g_bagg)[j] = make_float4(0.f, 0.f, 0.f, 0.f);
    } else {
        int e = (b - rblocks - zblocks) * 256 + t;
        if (e < n_edges) atomicAdd(&g_hist[src[e]], 1);
    }
}

// ---------------------------------------------------------------------------
// K2: per-block exclusive scan (block-local); totals to g_bsum; zeroes g_hist
// ---------------------------------------------------------------------------
__global__ __launch_bounds__(SCAN_T) void scan1_kernel(int n) {
    __shared__ int wsum[32];
    int t = threadIdx.x;
    int base = blockIdx.x * SCAN_B + t * SCAN_E;
    int v[SCAN_E];
    int local = 0;
    #pragma unroll
    for (int j = 0; j < SCAN_E; j++) {
        int i = base + j;
        v[j] = (i < n) ? g_hist[i] : 0;
        if (i < n) g_hist[i] = 0;          // becomes the scatter cursor
        local += v[j];
    }
    int lane = t & 31, w = t >> 5;
    int inc = local;
    #pragma unroll
    for (int d = 1; d < 32; d <<= 1) {
        int x = __shfl_up_sync(0xFFFFFFFF, inc, d);
        if (lane >= d) inc += x;
    }
    if (lane == 31) wsum[w] = inc;
    __syncthreads();
    if (t < 32) {
        int x = wsum[t];
        #pragma unroll
        for (int d = 1; d < 32; d <<= 1) {
            int y = __shfl_up_sync(0xFFFFFFFF, x, d);
            if (t >= d) x += y;
        }
        wsum[t] = x;
    }
    __syncthreads();
    int run = inc - local + ((w > 0) ? wsum[w - 1] : 0);
    #pragma unroll
    for (int j = 0; j < SCAN_E; j++) {
        if (base + j < n) g_start[base + j] = run;
        run += v[j];
    }
    if (t == SCAN_T - 1) g_bsum[blockIdx.x] = run;
}

// warp-scan of g_bsum into smem offsets
__device__ __forceinline__ void load_block_offsets(int* off, int t, int nsb) {
    if (t < 32) {
        int x = (t < nsb) ? g_bsum[t] : 0;
        int inc = x;
        #pragma unroll
        for (int d = 1; d < 32; d <<= 1) {
            int y = __shfl_up_sync(0xFFFFFFFF, inc, d);
            if (t >= d) inc += y;
        }
        off[t] = inc - x;
    }
}

// vec4 global reduction-add (no return)
__device__ __forceinline__ void red_add_v4(float* p, float a, float b, float c, float d) {
    asm volatile("red.global.add.v4.f32 [%0], {%1, %2, %3, %4};"
                 :: "l"(p), "f"(a), "f"(b), "f"(c), "f"(d) : "memory");
}

// ---------------------------------------------------------------------------
// FFMA2 helper (broadcast W row from smem)
// ---------------------------------------------------------------------------
__device__ __forceinline__ void fma2_step(unsigned long long* acc,
                                          const float* wrow, float xv) {
    unsigned long long xx;
    asm("mov.b64 %0, {%1, %1};" : "=l"(xx) : "f"(xv));
    const ulonglong2* w2 = reinterpret_cast<const ulonglong2*>(wrow);
    #pragma unroll
    for (int j = 0; j < 16; j++) {
        ulonglong2 wv = w2[j];
        asm("fma.rn.f32x2 %0, %1, %2, %0;" : "+l"(acc[2 * j + 0]) : "l"(xx), "l"(wv.x));
        asm("fma.rn.f32x2 %0, %1, %2, %0;" : "+l"(acc[2 * j + 1]) : "l"(xx), "l"(wv.y));
    }
}

// ---------------------------------------------------------------------------
// K3: scatter ∪ proj (heterogeneous blocks, independent work).
// ---------------------------------------------------------------------------
__global__ __launch_bounds__(256) void scatter_proj_kernel(
    const float* __restrict__ w_s,
    const float* __restrict__ w_n,
    const int* __restrict__ src,
    const int* __restrict__ dst,
    const float* __restrict__ bond,
    int n_nodes, int n_edges, int pblocks, int nsb) {

    __shared__ __align__(16) float Wsh[FP * 128];   // 43008 B
    __shared__ int off[32];

    int t = threadIdx.x;

    if ((int)blockIdx.x < pblocks) {
        // ---- proj: [Ps|Y] = featp @ [w_s|Wn81], K=84, N=128 ----
        #pragma unroll
        for (int r = 0; r < 42; r++) {              // 42*256 == 84*128
            int idx = r * 256 + t;
            int k = idx >> 7;
            int c = idx & 127;
            float v = 0.f;
            if (k < NF) v = (c < OC) ? __ldg(w_s + k * OC + c)
                                     : __ldg(w_n + k * OC + (c - OC));
            Wsh[idx] = v;
        }
        __syncthreads();

        int half = t >> 7;
        int node = blockIdx.x * 128 + (t & 127);
        if (node >= n_nodes) return;

        const float4* xrow = reinterpret_cast<const float4*>(g_featp + (size_t)node * FP);
        const float* wbase = Wsh + half * OC;

        unsigned long long acc[32];
        #pragma unroll
        for (int j = 0; j < 32; j++) acc[j] = 0ull;

        float4 xv = __ldg(xrow);
        #pragma unroll 3
        for (int i = 0; i < 21; i++) {
            float4 cur = xv;
            if (i + 1 < 21) xv = __ldg(xrow + i + 1);
            fma2_step(acc, wbase + (i * 4 + 0) * 128, cur.x);
            fma2_step(acc, wbase + (i * 4 + 1) * 128, cur.y);
            fma2_step(acc, wbase + (i * 4 + 2) * 128, cur.z);
            fma2_step(acc, wbase + (i * 4 + 3) * 128, cur.w);
        }

        float* orow = (half ? g_Y : g_Ps) + (size_t)node * OC;
        #pragma unroll
        for (int j = 0; j < 16; j++) {
            float x0, x1, x2, x3;
            asm("mov.b64 {%0, %1}, %2;" : "=f"(x0), "=f"(x1) : "l"(acc[2 * j + 0]));
            asm("mov.b64 {%0, %1}, %2;" : "=f"(x2), "=f"(x3) : "l"(acc[2 * j + 1]));
            reinterpret_cast<float4*>(orow)[j] = make_float4(x0, x1, x2, x3);
        }
    } else {
        // ---- scatter + bond fold ----
        load_block_offsets(off, t, nsb);
        __syncthreads();

        int e = (blockIdx.x - pblocks) * 256 + t;
        if (e >= n_edges) return;
        int s = __ldg(src + e);
        int d = __ldg(dst + e);
        float4 cs = __ldg(reinterpret_cast<const float4*>(g_featp + (size_t)s * FP));
        float4 cd = __ldg(reinterpret_cast<const float4*>(g_featp + (size_t)d * FP));
        float dx = cs.x - cd.x, dy = cs.y - cd.y, dz = cs.z - cd.z;
        float dd = dx * dx + dy * dy + dz * dz;
        float sc = (dd > 0.f) ? __frcp_rn(dd) : 10000.f;
        int pos = __ldg(g_start + s) + off[s >> 12] + atomicAdd(&g_hist[s], 1);
        g_sorted[pos] = make_int2(d * (OC * 4), __float_as_int(sc));

        // bond row: sequential 88B read, folded into g_bagg[s] via 6 v4 REDs
        const float2* br = reinterpret_cast<const float2*>(bond + (size_t)e * NB);
        float2 b0 = __ldg(br + 0), b1 = __ldg(br + 1), b2 = __ldg(br + 2);
        float2 b3 = __ldg(br + 3), b4 = __ldg(br + 4), b5 = __ldg(br + 5);
        float2 b6 = __ldg(br + 6), b7 = __ldg(br + 7), b8 = __ldg(br + 8);
        float2 b9 = __ldg(br + 9), b10 = __ldg(br + 10);
        float* bp = g_bagg + (size_t)s * BGP;
        red_add_v4(bp + 0,  b0.x, b0.y, b1.x, b1.y);
        red_add_v4(bp + 4,  b2.x, b2.y, b3.x, b3.y);
        red_add_v4(bp + 8,  b4.x, b4.y, b5.x, b5.y);
        red_add_v4(bp + 12, b6.x, b6.y, b7.x, b7.y);
        red_add_v4(bp + 16, b8.x, b8.y, b9.x, b9.y);
        red_add_v4(bp + 20, b10.x, b10.y, 0.f, 0.f);
    }
}

// ---------------------------------------------------------------------------
// K4: agg + combine. Warp per node; HALF-WARP per edge (even/odd), lane owns
// 4 channels (float4). Cross-half merge via 5 SHFLs; epilogue on lanes 0-15
// in float4. Re-zeroes g_hist for graph replay.
// ---------------------------------------------------------------------------
__global__ __launch_bounds__(256) void aggcomb_kernel(
    const float* __restrict__ w_n,   // [103][64]
    float* __restrict__ out,
    int n_nodes, int n_edges, int nsb) {

    __shared__ __align__(16) float Wc[25 * OC];   // rows 0..21 Wb, 22..24 Wn[0..2]
    __shared__ int off[32];
    __shared__ float bsh[8][NB];

    int t = threadIdx.x;
    for (int idx = t; idx < 25 * OC; idx += 256) {
        int k = idx >> 6;
        int c = idx & (OC - 1);
        Wc[idx] = (k < NB) ? __ldg(w_n + (NF + k) * OC + c)
                           : __ldg(w_n + (k - NB) * OC + c);
    }
    load_block_offsets(off, t, nsb);
    __syncthreads();

    int wid = t >> 5;
    int lane = t & 31;
    int n = (int)(blockIdx.x * 8 + wid);
    if (n >= n_nodes) return;

    int h = lane >> 4;          // edge-parity half
    int cl = lane & 15;         // float4 channel group (channels 4cl..4cl+3)

    int beg = __ldg(g_start + n) + off[n >> 12];
    int end = (n + 1 < n_nodes) ? (__ldg(g_start + n + 1) + off[(n + 1) >> 12])
                                : n_edges;

    const char* Yb = reinterpret_cast<const char*>(g_Y);

    float4 ay = make_float4(0.f, 0.f, 0.f, 0.f);
    float ac = 0.f;

    int i = beg + h;
    for (; i + 2 < end; i += 4) {       // 2 edges per half in flight
        int2 r0 = __ldg(g_sorted + i);
        int2 r1 = __ldg(g_sorted + i + 2);
        float4 y0 = __ldg(reinterpret_cast<const float4*>(Yb + (unsigned)r0.x) + cl);
        float4 y1 = __ldg(reinterpret_cast<const float4*>(Yb + (unsigned)r1.x) + cl);
        float s0 = __int_as_float(r0.y);
        float s1 = __int_as_float(r1.y);
        ay.x += s0 * y0.x + s1 * y1.x;
        ay.y += s0 * y0.y + s1 * y1.y;
        ay.z += s0 * y0.z + s1 * y1.z;
        ay.w += s0 * y0.w + s1 * y1.w;
        ac += s0 + s1;
    }
    for (; i < end; i += 2) {
        int2 r = __ldg(g_sorted + i);
        float4 y = __ldg(reinterpret_cast<const float4*>(Yb + (unsigned)r.x) + cl);
        float s = __int_as_float(r.y);
        ay.x += s * y.x;
        ay.y += s * y.y;
        ay.z += s * y.z;
        ay.w += s * y.w;
        ac += s;
    }

    // merge halves (lanes 0-15 end up with totals)
    ay.x += __shfl_down_sync(0xFFFFFFFF, ay.x, 16);
    ay.y += __shfl_down_sync(0xFFFFFFFF, ay.y, 16);
    ay.z += __shfl_down_sync(0xFFFFFFFF, ay.z, 16);
    ay.w += __shfl_down_sync(0xFFFFFFFF, ay.w, 16);
    ac   += __shfl_down_sync(0xFFFFFFFF, ac, 16);

    if (lane == 0) g_hist[n] = 0;        // reset cursor for next graph replay

    // bagg: sequential 88B read (11 lanes x float2) -> smem
    if (lane < 11) {
        float2 bv = __ldg(reinterpret_cast<const float2*>(g_bagg + (size_t)n * BGP) + lane);
        bsh[wid][2 * lane] = bv.x;
        bsh[wid][2 * lane + 1] = bv.y;
    }
    __syncwarp();

    // epilogue on lanes 0-15, float4 per lane (channels 4cl..4cl+3)
    if (h == 0) {
        const float4* ps4 = reinterpret_cast<const float4*>(g_Ps + (size_t)n * OC);
        const float4* y4 = reinterpret_cast<const float4*>(g_Y + (size_t)n * OC);
        const float4* Wc4 = reinterpret_cast<const float4*>(Wc);
        float4 fh = __ldg(reinterpret_cast<const float4*>(g_featp + (size_t)n * FP));
        float cn = ac;

        float4 ps = __ldg(ps4 + cl);
        float4 yy = __ldg(y4 + cl);
        float4 r;
        r.x = ps.x + ay.x + cn * yy.x;
        r.y = ps.y + ay.y + cn * yy.y;
        r.z = ps.z + ay.z + cn * yy.z;
        r.w = ps.w + ay.w + cn * yy.w;

        float4 w0 = Wc4[22 * 16 + cl];
        float4 w1 = Wc4[23 * 16 + cl];
        float4 w2 = Wc4[24 * 16 + cl];
        r.x -= cn * (fh.x * w0.x + fh.y * w1.x + fh.z * w2.x);
        r.y -= cn * (fh.x * w0.y + fh.y * w1.y + fh.z * w2.y);
        r.z -= cn * (fh.x * w0.z + fh.y * w1.z + fh.z * w2.z);
        r.w -= cn * (fh.x * w0.w + fh.y * w1.w + fh.z * w2.w);

        #pragma unroll
        for (int k = 0; k < NB; k++) {
            float bk = bsh[wid][k];
            float4 wk = Wc4[k * 16 + cl];
            r.x += bk * wk.x;
            r.y += bk * wk.y;
            r.z += bk * wk.z;
            r.w += bk * wk.w;
        }

        reinterpret_cast<float4*>(out + (size_t)n * OC)[cl] = r;
    }
}

// ---------------------------------------------------------------------------
extern "C" void kernel_launch(void* const* d_in, const int* in_sizes, int n_in,
                              void* d_out, int out_size) {
    const float* feat = (const float*)d_in[0];
    const float* bond = (const float*)d_in[1];
    const float* w_s  = (const float*)d_in[2];
    const float* w_n  = (const float*)d_in[3];
    const int*   src  = (const int*)d_in[4];
    const int*   dst  = (const int*)d_in[5];
    float* out = (float*)d_out;

    int n_nodes = in_sizes[0] / NF;
    int n_edges = in_sizes[4];
    int nsb = (n_nodes + SCAN_B - 1) / SCAN_B;        // 25

    int rblocks = (n_nodes * (FP / 4) + 255) / 256;   // repack
    int zblocks = (n_nodes * (BGP / 4) + 255) / 256;  // zero bagg
    int hblocks = (n_edges + 255) / 256;              // hist
    int pblocks = (n_nodes + 127) / 128;              // proj
    int sblocks = (n_edges + 255) / 256;              // scatter

    repack_hist_kernel<<<rblocks + zblocks + hblocks, 256>>>(
        feat, src, n_nodes, n_edges, rblocks, zblocks);
    scan1_kernel<<<nsb, SCAN_T>>>(n_nodes);
    scatter_proj_kernel<<<pblocks + sblocks, 256>>>(w_s, w_n, src, dst, bond,
                                                    n_nodes, n_edges, pblocks, nsb);
    aggcomb_kernel<<<(n_nodes + 7) / 8, 256>>>(w_n, out, n_nodes, n_edges, nsb);
}

// round 15
// speedup vs baseline: 1.1000x; 1.1000x over previous
#include <cuda_runtime.h>
#include <cuda_fp16.h>

// RuleGraphConvLayer — GB300 sm_103a, round 15
//
// Y = feat @ Wn81 pre-projection:
//   out[n] = Ps[n] + sum_e s_e*Y[dst_e] + c_n*(Y[n] - f0*Wn0 - f1*Wn1 - f2*Wn2)
//            + bagg[n] @ Wb
//
// R15 = R13 (aggcomb mapping reverted from R14) + fp16 Y gather:
//   proj additionally writes g_Yh (fp16, 128B/row = ONE L1 line) and aggcomb
//   gathers from it — 1 wavefront/edge instead of 2 (measured wf-bound at
//   67us). Accumulation stays fp32; only the gathered Y terms are fp16
//   (eps ~5e-4 on the aggY component; rel_err gate is 1e-3).
// 4 launches: repack+zero+hist | scan1 | scatter∪proj(+bond REDs) | aggcomb.

#define NF 81
#define FP 84      // padded feat pitch (336 B, 21 float4)
#define NB 22
#define BGP 24     // bagg pitch (96 B)
#define OC 64

#define MAX_NODES 100000
#define MAX_EDGES 800000

#define SCAN_T 1024
#define SCAN_E 4
#define SCAN_B (SCAN_T * SCAN_E)   // 4096

__device__ __align__(16) float g_featp[MAX_NODES * FP];
__device__ __align__(16) float g_Y[MAX_NODES * OC];
__device__ __align__(16) __half g_Yh[MAX_NODES * OC];   // fp16 copy, 128B rows
__device__ __align__(16) float g_Ps[MAX_NODES * OC];
__device__ __align__(16) float g_bagg[MAX_NODES * BGP];
__device__ __align__(8)  int2  g_sorted[MAX_EDGES];     // {dst*128, s_bits}
__device__ int g_hist[MAX_NODES];      // zero at load; scan1 zeroes; K4 re-zeroes
__device__ int g_start[MAX_NODES];     // block-LOCAL exclusive prefix
__device__ int g_bsum[64];

// ---------------------------------------------------------------------------
// K1: repack feat -> g_featp | zero g_bagg | src histogram  (3 block flavors)
// ---------------------------------------------------------------------------
__global__ void repack_hist_kernel(const float* __restrict__ feat,
                                   const int* __restrict__ src,
                                   int n_nodes, int n_edges,
                                   int rblocks, int zblocks) {
    int b = blockIdx.x;
    int t = threadIdx.x;
    if (b < rblocks) {
        int j = b * 256 + t;
        int total = n_nodes * (FP / 4);
        if (j < total) {
            int n = j / (FP / 4);
            int q = j - n * (FP / 4);
            int k = q * 4;
            const float* fr = feat + (size_t)n * NF;
            float4 v;
            v.x = (k + 0 < NF) ? __ldg(fr + k + 0) : 0.f;
            v.y = (k + 1 < NF) ? __ldg(fr + k + 1) : 0.f;
            v.z = (k + 2 < NF) ? __ldg(fr + k + 2) : 0.f;
            v.w = (k + 3 < NF) ? __ldg(fr + k + 3) : 0.f;
            reinterpret_cast<float4*>(g_featp)[j] = v;
        }
    } else if (b < rblocks + zblocks) {
        int j = (b - rblocks) * 256 + t;
        if (j < n_nodes * (BGP / 4))
            reinterpret_cast<float4*>(g_bagg)[j] = make_float4(0.f, 0.f, 0.f, 0.f);
    } else {
        int e = (b - rblocks - zblocks) * 256 + t;
        if (e < n_edges) atomicAdd(&g_hist[src[e]], 1);
    }
}

// ---------------------------------------------------------------------------
// K2: per-block exclusive scan (block-local); totals to g_bsum; zeroes g_hist
// ---------------------------------------------------------------------------
__global__ __launch_bounds__(SCAN_T) void scan1_kernel(int n) {
    __shared__ int wsum[32];
    int t = threadIdx.x;
    int base = blockIdx.x * SCAN_B + t * SCAN_E;
    int v[SCAN_E];
    int local = 0;
    #pragma unroll
    for (int j = 0; j < SCAN_E; j++) {
        int i = base + j;
        v[j] = (i < n) ? g_hist[i] : 0;
        if (i < n) g_hist[i] = 0;          // becomes the scatter cursor
        local += v[j];
    }
    int lane = t & 31, w = t >> 5;
    int inc = local;
    #pragma unroll
    for (int d = 1; d < 32; d <<= 1) {
        int x = __shfl_up_sync(0xFFFFFFFF, inc, d);
        if (lane >= d) inc += x;
    }
    if (lane == 31) wsum[w] = inc;
    __syncthreads();
    if (t < 32) {
        int x = wsum[t];
        #pragma unroll
        for (int d = 1; d < 32; d <<= 1) {
            int y = __shfl_up_sync(0xFFFFFFFF, x, d);
            if (t >= d) x += y;
        }
        wsum[t] = x;
    }
    __syncthreads();
    int run = inc - local + ((w > 0) ? wsum[w - 1] : 0);
    #pragma unroll
    for (int j = 0; j < SCAN_E; j++) {
        if (base + j < n) g_start[base + j] = run;
        run += v[j];
    }
    if (t == SCAN_T - 1) g_bsum[blockIdx.x] = run;
}

// warp-scan of g_bsum into smem offsets
__device__ __forceinline__ void load_block_offsets(int* off, int t, int nsb) {
    if (t < 32) {
        int x = (t < nsb) ? g_bsum[t] : 0;
        int inc = x;
        #pragma unroll
        for (int d = 1; d < 32; d <<= 1) {
            int y = __shfl_up_sync(0xFFFFFFFF, inc, d);
            if (t >= d) inc += y;
        }
        off[t] = inc - x;
    }
}

// vec4 global reduction-add (no return)
__device__ __forceinline__ void red_add_v4(float* p, float a, float b, float c, float d) {
    asm volatile("red.global.add.v4.f32 [%0], {%1, %2, %3, %4};"
                 :: "l"(p), "f"(a), "f"(b), "f"(c), "f"(d) : "memory");
}

// ---------------------------------------------------------------------------
// FFMA2 helper (broadcast W row from smem)
// ---------------------------------------------------------------------------
__device__ __forceinline__ void fma2_step(unsigned long long* acc,
                                          const float* wrow, float xv) {
    unsigned long long xx;
    asm("mov.b64 %0, {%1, %1};" : "=l"(xx) : "f"(xv));
    const ulonglong2* w2 = reinterpret_cast<const ulonglong2*>(wrow);
    #pragma unroll
    for (int j = 0; j < 16; j++) {
        ulonglong2 wv = w2[j];
        asm("fma.rn.f32x2 %0, %1, %2, %0;" : "+l"(acc[2 * j + 0]) : "l"(xx), "l"(wv.x));
        asm("fma.rn.f32x2 %0, %1, %2, %0;" : "+l"(acc[2 * j + 1]) : "l"(xx), "l"(wv.y));
    }
}

// ---------------------------------------------------------------------------
// K3: scatter ∪ proj (heterogeneous blocks, independent work).
//   proj: [Ps|Y] = featp @ [w_s|Wn81], K=84, N=128; Y also written as fp16
//   scatter: s_e, int2 record, bond row folded into g_bagg via 6 v4 REDs
// ---------------------------------------------------------------------------
__global__ __launch_bounds__(256) void scatter_proj_kernel(
    const float* __restrict__ w_s,
    const float* __restrict__ w_n,
    const int* __restrict__ src,
    const int* __restrict__ dst,
    const float* __restrict__ bond,
    int n_nodes, int n_edges, int pblocks, int nsb) {

    __shared__ __align__(16) float Wsh[FP * 128];   // 43008 B
    __shared__ int off[32];

    int t = threadIdx.x;

    if ((int)blockIdx.x < pblocks) {
        // ---- proj ----
        #pragma unroll
        for (int r = 0; r < 42; r++) {              // 42*256 == 84*128
            int idx = r * 256 + t;
            int k = idx >> 7;
            int c = idx & 127;
            float v = 0.f;
            if (k < NF) v = (c < OC) ? __ldg(w_s + k * OC + c)
                                     : __ldg(w_n + k * OC + (c - OC));
            Wsh[idx] = v;
        }
        __syncthreads();

        int half = t >> 7;
        int node = blockIdx.x * 128 + (t & 127);
        if (node >= n_nodes) return;

        const float4* xrow = reinterpret_cast<const float4*>(g_featp + (size_t)node * FP);
        const float* wbase = Wsh + half * OC;

        unsigned long long acc[32];
        #pragma unroll
        for (int j = 0; j < 32; j++) acc[j] = 0ull;

        float4 xv = __ldg(xrow);
        #pragma unroll 3
        for (int i = 0; i < 21; i++) {
            float4 cur = xv;
            if (i + 1 < 21) xv = __ldg(xrow + i + 1);
            fma2_step(acc, wbase + (i * 4 + 0) * 128, cur.x);
            fma2_step(acc, wbase + (i * 4 + 1) * 128, cur.y);
            fma2_step(acc, wbase + (i * 4 + 2) * 128, cur.z);
            fma2_step(acc, wbase + (i * 4 + 3) * 128, cur.w);
        }

        float* orow = (half ? g_Y : g_Ps) + (size_t)node * OC;
        uint2* yhrow = reinterpret_cast<uint2*>(g_Yh + (size_t)node * OC);
        #pragma unroll
        for (int j = 0; j < 16; j++) {
            float x0, x1, x2, x3;
            asm("mov.b64 {%0, %1}, %2;" : "=f"(x0), "=f"(x1) : "l"(acc[2 * j + 0]));
            asm("mov.b64 {%0, %1}, %2;" : "=f"(x2), "=f"(x3) : "l"(acc[2 * j + 1]));
            reinterpret_cast<float4*>(orow)[j] = make_float4(x0, x1, x2, x3);
            if (half) {
                __half2 h01 = __floats2half2_rn(x0, x1);
                __half2 h23 = __floats2half2_rn(x2, x3);
                uint2 hh;
                hh.x = *reinterpret_cast<unsigned*>(&h01);
                hh.y = *reinterpret_cast<unsigned*>(&h23);
                yhrow[j] = hh;
            }
        }
    } else {
        // ---- scatter + bond fold ----
        load_block_offsets(off, t, nsb);
        __syncthreads();

        int e = (blockIdx.x - pblocks) * 256 + t;
        if (e >= n_edges) return;
        int s = __ldg(src + e);
        int d = __ldg(dst + e);
        float4 cs = __ldg(reinterpret_cast<const float4*>(g_featp + (size_t)s * FP));
        float4 cd = __ldg(reinterpret_cast<const float4*>(g_featp + (size_t)d * FP));
        float dx = cs.x - cd.x, dy = cs.y - cd.y, dz = cs.z - cd.z;
        float dd = dx * dx + dy * dy + dz * dz;
        float sc = (dd > 0.f) ? __frcp_rn(dd) : 10000.f;
        int pos = __ldg(g_start + s) + off[s >> 12] + atomicAdd(&g_hist[s], 1);
        g_sorted[pos] = make_int2(d * (OC * 2), __float_as_int(sc));   // fp16 row: 128B

        // bond row: sequential 88B read, folded into g_bagg[s] via 6 v4 REDs
        const float2* br = reinterpret_cast<const float2*>(bond + (size_t)e * NB);
        float2 b0 = __ldg(br + 0), b1 = __ldg(br + 1), b2 = __ldg(br + 2);
        float2 b3 = __ldg(br + 3), b4 = __ldg(br + 4), b5 = __ldg(br + 5);
        float2 b6 = __ldg(br + 6), b7 = __ldg(br + 7), b8 = __ldg(br + 8);
        float2 b9 = __ldg(br + 9), b10 = __ldg(br + 10);
        float* bp = g_bagg + (size_t)s * BGP;
        red_add_v4(bp + 0,  b0.x, b0.y, b1.x, b1.y);
        red_add_v4(bp + 4,  b2.x, b2.y, b3.x, b3.y);
        red_add_v4(bp + 8,  b4.x, b4.y, b5.x, b5.y);
        red_add_v4(bp + 12, b6.x, b6.y, b7.x, b7.y);
        red_add_v4(bp + 16, b8.x, b8.y, b9.x, b9.y);
        red_add_v4(bp + 20, b10.x, b10.y, 0.f, 0.f);
    }
}

// ---------------------------------------------------------------------------
// K4: agg + combine (R13 mapping). Warp per node; lane owns channels 2l,2l+1.
// Edge loop: 8B uniform record + ONE LDG.32 fp16 Y gather (128B row = 1 line).
// bagg read sequentially in the epilogue. Re-zeroes g_hist for graph replay.
// ---------------------------------------------------------------------------
__global__ __launch_bounds__(256) void aggcomb_kernel(
    const float* __restrict__ w_n,   // [103][64]
    float* __restrict__ out,
    int n_nodes, int n_edges, int nsb) {

    __shared__ __align__(16) float Wc[25 * OC];   // rows 0..21 Wb, 22..24 Wn[0..2]
    __shared__ int off[32];
    __shared__ float bsh[8][NB];

    int t = threadIdx.x;
    for (int idx = t; idx < 25 * OC; idx += 256) {
        int k = idx >> 6;
        int c = idx & (OC - 1);
        Wc[idx] = (k < NB) ? __ldg(w_n + (NF + k) * OC + c)
                           : __ldg(w_n + (k - NB) * OC + c);
    }
    load_block_offsets(off, t, nsb);
    __syncthreads();

    int wid = t >> 5;
    int lane = t & 31;
    int n = (int)(blockIdx.x * 8 + wid);
    if (n >= n_nodes) return;

    int beg = __ldg(g_start + n) + off[n >> 12];
    int end = (n + 1 < n_nodes) ? (__ldg(g_start + n + 1) + off[(n + 1) >> 12])
                                : n_edges;

    const char* Yb = reinterpret_cast<const char*>(g_Yh);

    float ay0 = 0.f, ay1 = 0.f, ac = 0.f;

    int i = beg;
    for (; i + 3 < end; i += 4) {
        int2 r[4];
        float2 y[4];
        #pragma unroll
        for (int j = 0; j < 4; j++) r[j] = __ldg(g_sorted + i + j);
        #pragma unroll
        for (int j = 0; j < 4; j++) {
            __half2 h = __ldg(reinterpret_cast<const __half2*>(Yb + (unsigned)r[j].x) + lane);
            y[j] = __half22float2(h);
        }
        #pragma unroll
        for (int j = 0; j < 4; j++) {
            float s = __int_as_float(r[j].y);
            ay0 += s * y[j].x;
            ay1 += s * y[j].y;
            ac += s;
        }
    }
    for (; i < end; i++) {
        int2 r = __ldg(g_sorted + i);
        __half2 h = __ldg(reinterpret_cast<const __half2*>(Yb + (unsigned)r.x) + lane);
        float2 y = __half22float2(h);
        float s = __int_as_float(r.y);
        ay0 += s * y.x;
        ay1 += s * y.y;
        ac += s;
    }

    if (lane == 0) g_hist[n] = 0;        // reset cursor for next graph replay

    // bagg: sequential 88B read (11 lanes x float2) -> smem broadcast
    if (lane < 11) {
        float2 bv = __ldg(reinterpret_cast<const float2*>(g_bagg + (size_t)n * BGP) + lane);
        bsh[wid][2 * lane] = bv.x;
        bsh[wid][2 * lane + 1] = bv.y;
    }
    __syncwarp();

    // combine (channels 2*lane, 2*lane+1):
    // out = Ps + aggY + c*Y - c*(f0..2 @ Wn[0..2]) + bagg @ Wb
    const float2* ps2 = reinterpret_cast<const float2*>(g_Ps + (size_t)n * OC);
    const float2* y2 = reinterpret_cast<const float2*>(g_Y + (size_t)n * OC);
    float4 fh = __ldg(reinterpret_cast<const float4*>(g_featp + (size_t)n * FP));
    float cn = ac;

    float2 ps = __ldg(ps2 + lane);
    float2 yy = __ldg(y2 + lane);
    float r0 = ps.x + ay0 + cn * yy.x;
    float r1 = ps.y + ay1 + cn * yy.y;

    float2 w0 = reinterpret_cast<const float2*>(Wc + 22 * OC)[lane];
    float2 w1 = reinterpret_cast<const float2*>(Wc + 23 * OC)[lane];
    float2 w2 = reinterpret_cast<const float2*>(Wc + 24 * OC)[lane];
    r0 -= cn * (fh.x * w0.x + fh.y * w1.x + fh.z * w2.x);
    r1 -= cn * (fh.x * w0.y + fh.y * w1.y + fh.z * w2.y);

    #pragma unroll
    for (int k = 0; k < NB; k++) {
        float bk = bsh[wid][k];
        float2 wk = reinterpret_cast<const float2*>(Wc + k * OC)[lane];
        r0 += bk * wk.x;
        r1 += bk * wk.y;
    }

    reinterpret_cast<float2*>(out + (size_t)n * OC)[lane] = make_float2(r0, r1);
}

// ---------------------------------------------------------------------------
extern "C" void kernel_launch(void* const* d_in, const int* in_sizes, int n_in,
                              void* d_out, int out_size) {
    const float* feat = (const float*)d_in[0];
    const float* bond = (const float*)d_in[1];
    const float* w_s  = (const float*)d_in[2];
    const float* w_n  = (const float*)d_in[3];
    const int*   src  = (const int*)d_in[4];
    const int*   dst  = (const int*)d_in[5];
    float* out = (float*)d_out;

    int n_nodes = in_sizes[0] / NF;
    int n_edges = in_sizes[4];
    int nsb = (n_nodes + SCAN_B - 1) / SCAN_B;        // 25

    int rblocks = (n_nodes * (FP / 4) + 255) / 256;   // repack
    int zblocks = (n_nodes * (BGP / 4) + 255) / 256;  // zero bagg
    int hblocks = (n_edges + 255) / 256;              // hist
    int pblocks = (n_nodes + 127) / 128;              // proj
    int sblocks = (n_edges + 255) / 256;              // scatter

    repack_hist_kernel<<<rblocks + zblocks + hblocks, 256>>>(
        feat, src, n_nodes, n_edges, rblocks, zblocks);
    scan1_kernel<<<nsb, SCAN_T>>>(n_nodes);
    scatter_proj_kernel<<<pblocks + sblocks, 256>>>(w_s, w_n, src, dst, bond,
                                                    n_nodes, n_edges, pblocks, nsb);
    aggcomb_kernel<<<(n_nodes + 7) / 8, 256>>>(w_n, out, n_nodes, n_edges, nsb);
}

// round 16
// speedup vs baseline: 1.1920x; 1.0837x over previous
#include <cuda_runtime.h>
#include <cuda_fp16.h>

// RuleGraphConvLayer — GB300 sm_103a, round 16
//
// Y = feat @ Wn81 pre-projection (stored ONLY as fp16):
//   out[n] = Ps[n] + sum_e s_e*Y[dst_e] + c_n*(Y[n] - f0*Wn0 - f1*Wn1 - f2*Wn2)
//            + bagg[n] @ Wb
//
// R16 = R15 minus the fp32 Y array: proj writes only g_Yh (fp16, 128B rows);
// aggcomb's combine epilogue reads its own Y row from g_Yh as well.
// -25MB traffic + lower L2 pressure for the random Yh gathers.
// 4 launches: repack+zero+hist | scan1 | scatter∪proj(+bond REDs) | aggcomb.

#define NF 81
#define FP 84      // padded feat pitch (336 B, 21 float4)
#define NB 22
#define BGP 24     // bagg pitch (96 B)
#define OC 64

#define MAX_NODES 100000
#define MAX_EDGES 800000

#define SCAN_T 1024
#define SCAN_E 4
#define SCAN_B (SCAN_T * SCAN_E)   // 4096

__device__ __align__(16) float g_featp[MAX_NODES * FP];
__device__ __align__(16) __half g_Yh[MAX_NODES * OC];   // fp16 Y, 128B rows
__device__ __align__(16) float g_Ps[MAX_NODES * OC];
__device__ __align__(16) float g_bagg[MAX_NODES * BGP];
__device__ __align__(8)  int2  g_sorted[MAX_EDGES];     // {dst*128, s_bits}
__device__ int g_hist[MAX_NODES];      // zero at load; scan1 zeroes; K4 re-zeroes
__device__ int g_start[MAX_NODES];     // block-LOCAL exclusive prefix
__device__ int g_bsum[64];

// ---------------------------------------------------------------------------
// K1: repack feat -> g_featp | zero g_bagg | src histogram  (3 block flavors)
// ---------------------------------------------------------------------------
__global__ void repack_hist_kernel(const float* __restrict__ feat,
                                   const int* __restrict__ src,
                                   int n_nodes, int n_edges,
                                   int rblocks, int zblocks) {
    int b = blockIdx.x;
    int t = threadIdx.x;
    if (b < rblocks) {
        int j = b * 256 + t;
        int total = n_nodes * (FP / 4);
        if (j < total) {
            int n = j / (FP / 4);
            int q = j - n * (FP / 4);
            int k = q * 4;
            const float* fr = feat + (size_t)n * NF;
            float4 v;
            v.x = (k + 0 < NF) ? __ldg(fr + k + 0) : 0.f;
            v.y = (k + 1 < NF) ? __ldg(fr + k + 1) : 0.f;
            v.z = (k + 2 < NF) ? __ldg(fr + k + 2) : 0.f;
            v.w = (k + 3 < NF) ? __ldg(fr + k + 3) : 0.f;
            reinterpret_cast<float4*>(g_featp)[j] = v;
        }
    } else if (b < rblocks + zblocks) {
        int j = (b - rblocks) * 256 + t;
        if (j < n_nodes * (BGP / 4))
            reinterpret_cast<float4*>(g_bagg)[j] = make_float4(0.f, 0.f, 0.f, 0.f);
    } else {
        int e = (b - rblocks - zblocks) * 256 + t;
        if (e < n_edges) atomicAdd(&g_hist[src[e]], 1);
    }
}

// ---------------------------------------------------------------------------
// K2: per-block exclusive scan (block-local); totals to g_bsum; zeroes g_hist
// ---------------------------------------------------------------------------
__global__ __launch_bounds__(SCAN_T) void scan1_kernel(int n) {
    __shared__ int wsum[32];
    int t = threadIdx.x;
    int base = blockIdx.x * SCAN_B + t * SCAN_E;
    int v[SCAN_E];
    int local = 0;
    #pragma unroll
    for (int j = 0; j < SCAN_E; j++) {
        int i = base + j;
        v[j] = (i < n) ? g_hist[i] : 0;
        if (i < n) g_hist[i] = 0;          // becomes the scatter cursor
        local += v[j];
    }
    int lane = t & 31, w = t >> 5;
    int inc = local;
    #pragma unroll
    for (int d = 1; d < 32; d <<= 1) {
        int x = __shfl_up_sync(0xFFFFFFFF, inc, d);
        if (lane >= d) inc += x;
    }
    if (lane == 31) wsum[w] = inc;
    __syncthreads();
    if (t < 32) {
        int x = wsum[t];
        #pragma unroll
        for (int d = 1; d < 32; d <<= 1) {
            int y = __shfl_up_sync(0xFFFFFFFF, x, d);
            if (t >= d) x += y;
        }
        wsum[t] = x;
    }
    __syncthreads();
    int run = inc - local + ((w > 0) ? wsum[w - 1] : 0);
    #pragma unroll
    for (int j = 0; j < SCAN_E; j++) {
        if (base + j < n) g_start[base + j] = run;
        run += v[j];
    }
    if (t == SCAN_T - 1) g_bsum[blockIdx.x] = run;
}

// warp-scan of g_bsum into smem offsets
__device__ __forceinline__ void load_block_offsets(int* off, int t, int nsb) {
    if (t < 32) {
        int x = (t < nsb) ? g_bsum[t] : 0;
        int inc = x;
        #pragma unroll
        for (int d = 1; d < 32; d <<= 1) {
            int y = __shfl_up_sync(0xFFFFFFFF, inc, d);
            if (t >= d) inc += y;
        }
        off[t] = inc - x;
    }
}

// vec4 global reduction-add (no return)
__device__ __forceinline__ void red_add_v4(float* p, float a, float b, float c, float d) {
    asm volatile("red.global.add.v4.f32 [%0], {%1, %2, %3, %4};"
                 :: "l"(p), "f"(a), "f"(b), "f"(c), "f"(d) : "memory");
}

// ---------------------------------------------------------------------------
// FFMA2 helper (broadcast W row from smem)
// ---------------------------------------------------------------------------
__device__ __forceinline__ void fma2_step(unsigned long long* acc,
                                          const float* wrow, float xv) {
    unsigned long long xx;
    asm("mov.b64 %0, {%1, %1};" : "=l"(xx) : "f"(xv));
    const ulonglong2* w2 = reinterpret_cast<const ulonglong2*>(wrow);
    #pragma unroll
    for (int j = 0; j < 16; j++) {
        ulonglong2 wv = w2[j];
        asm("fma.rn.f32x2 %0, %1, %2, %0;" : "+l"(acc[2 * j + 0]) : "l"(xx), "l"(wv.x));
        asm("fma.rn.f32x2 %0, %1, %2, %0;" : "+l"(acc[2 * j + 1]) : "l"(xx), "l"(wv.y));
    }
}

// ---------------------------------------------------------------------------
// K3: scatter ∪ proj (heterogeneous blocks, independent work).
//   proj: [Ps|Y] = featp @ [w_s|Wn81], K=84, N=128; Ps fp32, Y fp16-only
//   scatter: s_e, int2 record, bond row folded into g_bagg via 6 v4 REDs
// ---------------------------------------------------------------------------
__global__ __launch_bounds__(256) void scatter_proj_kernel(
    const float* __restrict__ w_s,
    const float* __restrict__ w_n,
    const int* __restrict__ src,
    const int* __restrict__ dst,
    const float* __restrict__ bond,
    int n_nodes, int n_edges, int pblocks, int nsb) {

    __shared__ __align__(16) float Wsh[FP * 128];   // 43008 B
    __shared__ int off[32];

    int t = threadIdx.x;

    if ((int)blockIdx.x < pblocks) {
        // ---- proj ----
        #pragma unroll
        for (int r = 0; r < 42; r++) {              // 42*256 == 84*128
            int idx = r * 256 + t;
            int k = idx >> 7;
            int c = idx & 127;
            float v = 0.f;
            if (k < NF) v = (c < OC) ? __ldg(w_s + k * OC + c)
                                     : __ldg(w_n + k * OC + (c - OC));
            Wsh[idx] = v;
        }
        __syncthreads();

        int half = t >> 7;
        int node = blockIdx.x * 128 + (t & 127);
        if (node >= n_nodes) return;

        const float4* xrow = reinterpret_cast<const float4*>(g_featp + (size_t)node * FP);
        const float* wbase = Wsh + half * OC;

        unsigned long long acc[32];
        #pragma unroll
        for (int j = 0; j < 32; j++) acc[j] = 0ull;

        float4 xv = __ldg(xrow);
        #pragma unroll 3
        for (int i = 0; i < 21; i++) {
            float4 cur = xv;
            if (i + 1 < 21) xv = __ldg(xrow + i + 1);
            fma2_step(acc, wbase + (i * 4 + 0) * 128, cur.x);
            fma2_step(acc, wbase + (i * 4 + 1) * 128, cur.y);
            fma2_step(acc, wbase + (i * 4 + 2) * 128, cur.z);
            fma2_step(acc, wbase + (i * 4 + 3) * 128, cur.w);
        }

        if (half) {
            // Y: fp16 only (128B row)
            uint2* yhrow = reinterpret_cast<uint2*>(g_Yh + (size_t)node * OC);
            #pragma unroll
            for (int j = 0; j < 16; j++) {
                float x0, x1, x2, x3;
                asm("mov.b64 {%0, %1}, %2;" : "=f"(x0), "=f"(x1) : "l"(acc[2 * j + 0]));
                asm("mov.b64 {%0, %1}, %2;" : "=f"(x2), "=f"(x3) : "l"(acc[2 * j + 1]));
                __half2 h01 = __floats2half2_rn(x0, x1);
                __half2 h23 = __floats2half2_rn(x2, x3);
                uint2 hh;
                hh.x = *reinterpret_cast<unsigned*>(&h01);
                hh.y = *reinterpret_cast<unsigned*>(&h23);
                yhrow[j] = hh;
            }
        } else {
            float* orow = g_Ps + (size_t)node * OC;
            #pragma unroll
            for (int j = 0; j < 16; j++) {
                float x0, x1, x2, x3;
                asm("mov.b64 {%0, %1}, %2;" : "=f"(x0), "=f"(x1) : "l"(acc[2 * j + 0]));
                asm("mov.b64 {%0, %1}, %2;" : "=f"(x2), "=f"(x3) : "l"(acc[2 * j + 1]));
                reinterpret_cast<float4*>(orow)[j] = make_float4(x0, x1, x2, x3);
            }
        }
    } else {
        // ---- scatter + bond fold ----
        load_block_offsets(off, t, nsb);
        __syncthreads();

        int e = (blockIdx.x - pblocks) * 256 + t;
        if (e >= n_edges) return;
        int s = __ldg(src + e);
        int d = __ldg(dst + e);
        float4 cs = __ldg(reinterpret_cast<const float4*>(g_featp + (size_t)s * FP));
        float4 cd = __ldg(reinterpret_cast<const float4*>(g_featp + (size_t)d * FP));
        float dx = cs.x - cd.x, dy = cs.y - cd.y, dz = cs.z - cd.z;
        float dd = dx * dx + dy * dy + dz * dz;
        float sc = (dd > 0.f) ? __frcp_rn(dd) : 10000.f;
        int pos = __ldg(g_start + s) + off[s >> 12] + atomicAdd(&g_hist[s], 1);
        g_sorted[pos] = make_int2(d * (OC * 2), __float_as_int(sc));   // fp16 row: 128B

        // bond row: sequential 88B read, folded into g_bagg[s] via 6 v4 REDs
        const float2* br = reinterpret_cast<const float2*>(bond + (size_t)e * NB);
        float2 b0 = __ldg(br + 0), b1 = __ldg(br + 1), b2 = __ldg(br + 2);
        float2 b3 = __ldg(br + 3), b4 = __ldg(br + 4), b5 = __ldg(br + 5);
        float2 b6 = __ldg(br + 6), b7 = __ldg(br + 7), b8 = __ldg(br + 8);
        float2 b9 = __ldg(br + 9), b10 = __ldg(br + 10);
        float* bp = g_bagg + (size_t)s * BGP;
        red_add_v4(bp + 0,  b0.x, b0.y, b1.x, b1.y);
        red_add_v4(bp + 4,  b2.x, b2.y, b3.x, b3.y);
        red_add_v4(bp + 8,  b4.x, b4.y, b5.x, b5.y);
        red_add_v4(bp + 12, b6.x, b6.y, b7.x, b7.y);
        red_add_v4(bp + 16, b8.x, b8.y, b9.x, b9.y);
        red_add_v4(bp + 20, b10.x, b10.y, 0.f, 0.f);
    }
}

// ---------------------------------------------------------------------------
// K4: agg + combine. Warp per node; lane owns channels 2l,2l+1.
// Edge loop: 8B uniform record + ONE LDG.32 fp16 Y gather (128B row = 1 line).
// Combine epilogue also reads own Y from g_Yh. Re-zeroes g_hist.
// ---------------------------------------------------------------------------
__global__ __launch_bounds__(256) void aggcomb_kernel(
    const float* __restrict__ w_n,   // [103][64]
    float* __restrict__ out,
    int n_nodes, int n_edges, int nsb) {

    __shared__ __align__(16) float Wc[25 * OC];   // rows 0..21 Wb, 22..24 Wn[0..2]
    __shared__ int off[32];
    __shared__ float bsh[8][NB];

    int t = threadIdx.x;
    for (int idx = t; idx < 25 * OC; idx += 256) {
        int k = idx >> 6;
        int c = idx & (OC - 1);
        Wc[idx] = (k < NB) ? __ldg(w_n + (NF + k) * OC + c)
                           : __ldg(w_n + (k - NB) * OC + c);
    }
    load_block_offsets(off, t, nsb);
    __syncthreads();

    int wid = t >> 5;
    int lane = t & 31;
    int n = (int)(blockIdx.x * 8 + wid);
    if (n >= n_nodes) return;

    int beg = __ldg(g_start + n) + off[n >> 12];
    int end = (n + 1 < n_nodes) ? (__ldg(g_start + n + 1) + off[(n + 1) >> 12])
                                : n_edges;

    const char* Yb = reinterpret_cast<const char*>(g_Yh);

    float ay0 = 0.f, ay1 = 0.f, ac = 0.f;

    int i = beg;
    for (; i + 3 < end; i += 4) {
        int2 r[4];
        float2 y[4];
        #pragma unroll
        for (int j = 0; j < 4; j++) r[j] = __ldg(g_sorted + i + j);
        #pragma unroll
        for (int j = 0; j < 4; j++) {
            __half2 h = __ldg(reinterpret_cast<const __half2*>(Yb + (unsigned)r[j].x) + lane);
            y[j] = __half22float2(h);
        }
        #pragma unroll
        for (int j = 0; j < 4; j++) {
            float s = __int_as_float(r[j].y);
            ay0 += s * y[j].x;
            ay1 += s * y[j].y;
            ac += s;
        }
    }
    for (; i < end; i++) {
        int2 r = __ldg(g_sorted + i);
        __half2 h = __ldg(reinterpret_cast<const __half2*>(Yb + (unsigned)r.x) + lane);
        float2 y = __half22float2(h);
        float s = __int_as_float(r.y);
        ay0 += s * y.x;
        ay1 += s * y.y;
        ac += s;
    }

    if (lane == 0) g_hist[n] = 0;        // reset cursor for next graph replay

    // bagg: sequential 88B read (11 lanes x float2) -> smem broadcast
    if (lane < 11) {
        float2 bv = __ldg(reinterpret_cast<const float2*>(g_bagg + (size_t)n * BGP) + lane);
        bsh[wid][2 * lane] = bv.x;
        bsh[wid][2 * lane + 1] = bv.y;
    }
    __syncwarp();

    // combine (channels 2*lane, 2*lane+1):
    // out = Ps + aggY + c*Y - c*(f0..2 @ Wn[0..2]) + bagg @ Wb
    const float2* ps2 = reinterpret_cast<const float2*>(g_Ps + (size_t)n * OC);
    const __half2* yh2 = reinterpret_cast<const __half2*>(g_Yh + (size_t)n * OC);
    float4 fh = __ldg(reinterpret_cast<const float4*>(g_featp + (size_t)n * FP));
    float cn = ac;

    float2 ps = __ldg(ps2 + lane);
    float2 yy = __half22float2(__ldg(yh2 + lane));
    float r0 = ps.x + ay0 + cn * yy.x;
    float r1 = ps.y + ay1 + cn * yy.y;

    float2 w0 = reinterpret_cast<const float2*>(Wc + 22 * OC)[lane];
    float2 w1 = reinterpret_cast<const float2*>(Wc + 23 * OC)[lane];
    float2 w2 = reinterpret_cast<const float2*>(Wc + 24 * OC)[lane];
    r0 -= cn * (fh.x * w0.x + fh.y * w1.x + fh.z * w2.x);
    r1 -= cn * (fh.x * w0.y + fh.y * w1.y + fh.z * w2.y);

    #pragma unroll
    for (int k = 0; k < NB; k++) {
        float bk = bsh[wid][k];
        float2 wk = reinterpret_cast<const float2*>(Wc + k * OC)[lane];
        r0 += bk * wk.x;
        r1 += bk * wk.y;
    }

    reinterpret_cast<float2*>(out + (size_t)n * OC)[lane] = make_float2(r0, r1);
}

// ---------------------------------------------------------------------------
extern "C" void kernel_launch(void* const* d_in, const int* in_sizes, int n_in,
                              void* d_out, int out_size) {
    const float* feat = (const float*)d_in[0];
    const float* bond = (const float*)d_in[1];
    const float* w_s  = (const float*)d_in[2];
    const float* w_n  = (const float*)d_in[3];
    const int*   src  = (const int*)d_in[4];
    const int*   dst  = (const int*)d_in[5];
    float* out = (float*)d_out;

    int n_nodes = in_sizes[0] / NF;
    int n_edges = in_sizes[4];
    int nsb = (n_nodes + SCAN_B - 1) / SCAN_B;        // 25

    int rblocks = (n_nodes * (FP / 4) + 255) / 256;   // repack
    int zblocks = (n_nodes * (BGP / 4) + 255) / 256;  // zero bagg
    int hblocks = (n_edges + 255) / 256;              // hist
    int pblocks = (n_nodes + 127) / 128;              // proj
    int sblocks = (n_edges + 255) / 256;              // scatter

    repack_hist_kernel<<<rblocks + zblocks + hblocks, 256>>>(
        feat, src, n_nodes, n_edges, rblocks, zblocks);
    scan1_kernel<<<nsb, SCAN_T>>>(n_nodes);
    scatter_proj_kernel<<<pblocks + sblocks, 256>>>(w_s, w_n, src, dst, bond,
                                                    n_nodes, n_edges, pblocks, nsb);
    aggcomb_kernel<<<(n_nodes + 7) / 8, 256>>>(w_n, out, n_nodes, n_edges, nsb);
}